// round 2
// baseline (speedup 1.0000x reference)
#include <cuda_runtime.h>

// Problem constants (match reference)
#define NN   30000
#define EE   300000
#define NG   512
#define HID  600
#define INF  9
#define NT   128
#define CHID 256

// ---------------- device scratch (allocation-free rule: device globals) ----
__device__ float g_h[NN * HID];
__device__ float g_agg[NN * HID];
__device__ float g_t1[NN * HID];
__device__ float g_feats[NG * HID];
__device__ float g_z1[NG * CHID];
__device__ float g_z2[NG * CHID];

__device__ int g_src[EE];
__device__ int g_dst[EE];
__device__ int g_batch[NN];
__device__ int g_deg[NN];
__device__ int g_rowptr[NN + 1];
__device__ int g_cursor[NN];
__device__ int g_col[EE];
__device__ int g_is64;

// ---------------- index dtype detection + conversion ----------------------
// If edge_index serialized as int64, every u64 word has high 32 bits == 0
// (values in [0, 30000)). If int32, the "high word" is the next index, which
// is ~never zero 256 times in a row.
__global__ void k_detect(const unsigned long long* __restrict__ p) {
    if (threadIdx.x == 0 && blockIdx.x == 0) {
        int is64 = 1;
        for (int i = 0; i < 256; i++)
            if (p[i] >> 32) { is64 = 0; break; }
        g_is64 = is64;
    }
}

__global__ void k_convert(const void* __restrict__ edges,
                          const void* __restrict__ batch) {
    int i = blockIdx.x * blockDim.x + threadIdx.x;
    int is64 = g_is64;
    if (i < EE) {
        if (is64) {
            const long long* p = (const long long*)edges;
            g_src[i] = (int)p[i];
            g_dst[i] = (int)p[EE + i];
        } else {
            const int* p = (const int*)edges;
            g_src[i] = p[i];
            g_dst[i] = p[EE + i];
        }
    }
    if (i < NN) {
        if (is64) {
            const long long* p = (const long long*)batch;
            g_batch[i] = (int)p[i];
        } else {
            const int* p = (const int*)batch;
            g_batch[i] = p[i];
        }
    }
}

// ---------------- small utility kernels ------------------------------------
__global__ void k_zero_int(int* p, int n) {
    int i = blockIdx.x * blockDim.x + threadIdx.x;
    if (i < n) p[i] = 0;
}
__global__ void k_zero_float(float* p, int n) {
    int i = blockIdx.x * blockDim.x + threadIdx.x;
    if (i < n) p[i] = 0.f;
}
__global__ void k_copy_int(const int* __restrict__ a, int* __restrict__ b, int n) {
    int i = blockIdx.x * blockDim.x + threadIdx.x;
    if (i < n) b[i] = a[i];
}

// ---------------- CSR build (dst-major) ------------------------------------
__global__ void k_count(const int* __restrict__ dst, int* __restrict__ deg) {
    int i = blockIdx.x * blockDim.x + threadIdx.x;
    if (i < EE) atomicAdd(&deg[dst[i]], 1);
}

// single-block exclusive scan over n, 1024 threads
__global__ void k_scan(const int* __restrict__ in, int* __restrict__ out, int n) {
    __shared__ int s[1024];
    __shared__ int s_carry;
    int tid = threadIdx.x;
    if (tid == 0) s_carry = 0;
    __syncthreads();
    for (int base = 0; base < n; base += 1024) {
        int i = base + tid;
        int v = (i < n) ? in[i] : 0;
        s[tid] = v;
        __syncthreads();
        for (int off = 1; off < 1024; off <<= 1) {
            int t = (tid >= off) ? s[tid - off] : 0;
            __syncthreads();
            s[tid] += t;
            __syncthreads();
        }
        int c = s_carry;
        if (i < n) out[i] = c + s[tid] - v;
        __syncthreads();
        if (tid == 0) s_carry = c + s[1023];
        __syncthreads();
    }
    if (tid == 0) out[n] = s_carry;
}

__global__ void k_fill(const int* __restrict__ src, const int* __restrict__ dst,
                       int* __restrict__ cursor, int* __restrict__ col) {
    int i = blockIdx.x * blockDim.x + threadIdx.x;
    if (i < EE) {
        int p = atomicAdd(&cursor[dst[i]], 1);
        col[p] = src[i];
    }
}

// ---------------- aggregation: agg[n] = h[n] + sum_{s in nbrs(n)} h[s] -----
// Scalar path (layer 0, width 9)
__global__ void k_aggregate(const float* __restrict__ h, float* __restrict__ agg,
                            const int* __restrict__ rowptr,
                            const int* __restrict__ col, int width) {
    __shared__ int s_nbr[64];
    int node = blockIdx.x;
    int f = threadIdx.x;
    int CH = (blockDim.x < 64) ? blockDim.x : 64;
    int start = rowptr[node], end = rowptr[node + 1];
    float acc = (f < width) ? h[node * width + f] : 0.f;
    for (int base = start; base < end; base += CH) {
        int cnt = end - base;
        if (cnt > CH) cnt = CH;
        if ((int)threadIdx.x < cnt) s_nbr[threadIdx.x] = col[base + threadIdx.x];
        __syncthreads();
        if (f < width) {
            for (int j = 0; j < cnt; j++)
                acc += h[s_nbr[j] * width + f];
        }
        __syncthreads();
    }
    if (f < width) agg[node * width + f] = acc;
}

// Vectorized path for width == HID (600 floats = 150 float4, rows 16B-aligned)
__global__ void k_aggregate_v4(const float* __restrict__ h, float* __restrict__ agg,
                               const int* __restrict__ rowptr,
                               const int* __restrict__ col) {
    __shared__ int s_nbr[32];
    int node = blockIdx.x;
    int f4 = threadIdx.x;                  // 0..159, use first 150
    int start = rowptr[node], end = rowptr[node + 1];
    const float4* hv = (const float4*)h;
    float4 acc;
    if (f4 < 150) acc = hv[node * 150 + f4];
    else acc = make_float4(0.f, 0.f, 0.f, 0.f);
    for (int base = start; base < end; base += 32) {
        int cnt = end - base;
        if (cnt > 32) cnt = 32;
        if ((int)threadIdx.x < cnt) s_nbr[threadIdx.x] = col[base + threadIdx.x];
        __syncthreads();
        if (f4 < 150) {
            for (int j = 0; j < cnt; j++) {
                float4 v = hv[s_nbr[j] * 150 + f4];
                acc.x += v.x; acc.y += v.y; acc.z += v.z; acc.w += v.w;
            }
        }
        __syncthreads();
    }
    if (f4 < 150) ((float4*)agg)[node * 150 + f4] = acc;
}

// ---------------- pooling: feats[g] = sum_{n: batch[n]==g} h[n] ------------
__global__ void k_pool(const float* __restrict__ h, const int* __restrict__ batch,
                       float* __restrict__ feats) {
    int idx = blockIdx.x * blockDim.x + threadIdx.x;
    if (idx >= NN * HID) return;
    int n = idx / HID;
    int f = idx - n * HID;
    atomicAdd(&feats[batch[n] * HID + f], h[idx]);
}

// ---------------- SGEMM: C = act(A[M,K] @ B[K,N] + bias) -------------------
// 128x128 block tile, BK=8, 256 threads, 8x8 microtile (split 4+4 for
// conflict-free LDS.128 fragment loads).
#define BM 128
#define BN 128
#define BK 8

__global__ __launch_bounds__(256)
void k_sgemm(int M, int N, int K,
             const float* __restrict__ A, const float* __restrict__ B,
             const float* __restrict__ bias, float* __restrict__ C, int relu) {
    __shared__ float As[BK][BM + 4];
    __shared__ float Bs[BK][BN];

    int tid = threadIdx.x;
    int tx = tid & 15;       // 0..15 -> column groups
    int ty = tid >> 4;       // 0..15 -> row groups
    int m0 = blockIdx.y * BM;
    int n0 = blockIdx.x * BN;

    // interior-tile fast path predicates
    bool m_full = (m0 + BM <= M);
    bool n_full = (n0 + BN <= N);
    // K % 4 == 0 holds for all our K (9 is odd -> handled by scalar path below)
    bool k_vec = ((K & 3) == 0);

    float acc[8][8];
#pragma unroll
    for (int i = 0; i < 8; i++)
#pragma unroll
        for (int j = 0; j < 8; j++) acc[i][j] = 0.f;

    for (int k0 = 0; k0 < K; k0 += BK) {
        bool k_full = (k0 + BK <= K);
        // ---- load A tile (128x8), transposed into As[k][m] ----
        if (m_full && k_full && k_vec) {
            // thread e: row m = tid>>1, k-offset = (tid&1)*4; float4 along k
            int m = tid >> 1;
            int kk = (tid & 1) * 4;
            float4 v = *(const float4*)&A[(m0 + m) * K + k0 + kk];
            As[kk + 0][m] = v.x;
            As[kk + 1][m] = v.y;
            As[kk + 2][m] = v.z;
            As[kk + 3][m] = v.w;
        } else {
#pragma unroll
            for (int i = 0; i < 4; i++) {
                int e = tid * 4 + i;
                int m = e >> 3, k = e & 7;
                int gm = m0 + m, gk = k0 + k;
                As[k][m] = (gm < M && gk < K) ? A[gm * K + gk] : 0.f;
            }
        }
        // ---- load B tile (8x128) ----
        if (n_full && k_full) {
            // thread e covers 4 consecutive n: k = tid>>5, n = (tid&31)*4
            int k = tid >> 5;
            int n = (tid & 31) * 4;
            float4 v = *(const float4*)&B[(k0 + k) * N + n0 + n];
            *(float4*)&Bs[k][n] = v;
        } else {
#pragma unroll
            for (int i = 0; i < 4; i++) {
                int e = tid * 4 + i;
                int k = e >> 7, n = e & 127;
                int gn = n0 + n, gk = k0 + k;
                Bs[k][n] = (gn < N && gk < K) ? B[gk * N + gn] : 0.f;
            }
        }
        __syncthreads();

#pragma unroll
        for (int k = 0; k < BK; k++) {
            float4 a0 = *(const float4*)&As[k][ty * 4];
            float4 a1 = *(const float4*)&As[k][64 + ty * 4];
            float4 b0 = *(const float4*)&Bs[k][tx * 4];
            float4 b1 = *(const float4*)&Bs[k][64 + tx * 4];
            float a[8] = {a0.x, a0.y, a0.z, a0.w, a1.x, a1.y, a1.z, a1.w};
            float b[8] = {b0.x, b0.y, b0.z, b0.w, b1.x, b1.y, b1.z, b1.w};
#pragma unroll
            for (int i = 0; i < 8; i++)
#pragma unroll
                for (int j = 0; j < 8; j++)
                    acc[i][j] = fmaf(a[i], b[j], acc[i][j]);
        }
        __syncthreads();
    }

    // epilogue: bias + optional relu
#pragma unroll
    for (int i = 0; i < 8; i++) {
        int r = (i < 4) ? (ty * 4 + i) : (64 + ty * 4 + (i - 4));
        int gm = m0 + r;
        if (gm >= M) continue;
#pragma unroll
        for (int j = 0; j < 8; j++) {
            int c = (j < 4) ? (tx * 4 + j) : (64 + tx * 4 + (j - 4));
            int gn = n0 + c;
            if (gn >= N) continue;
            float v = acc[i][j] + bias[gn];
            if (relu) v = fmaxf(v, 0.f);
            C[gm * N + gn] = v;
        }
    }
}

// ---------------- host orchestration ---------------------------------------
static inline void sgemm(int M, int N, int K, const float* A, const float* B,
                         const float* bias, float* C, int relu) {
    dim3 grid((N + BN - 1) / BN, (M + BM - 1) / BM);
    k_sgemm<<<grid, 256>>>(M, N, K, A, B, bias, C, relu);
}

extern "C" void kernel_launch(void* const* d_in, const int* in_sizes, int n_in,
                              void* d_out, int out_size) {
    const float* x      = (const float*)d_in[0];
    const void*  edges  = d_in[1];
    const void*  batch  = d_in[2];
    const float* w1_0 = (const float*)d_in[3];
    const float* b1_0 = (const float*)d_in[4];
    const float* w2_0 = (const float*)d_in[5];
    const float* b2_0 = (const float*)d_in[6];
    const float* w1_r = (const float*)d_in[7];
    const float* b1_r = (const float*)d_in[8];
    const float* w2_r = (const float*)d_in[9];
    const float* b2_r = (const float*)d_in[10];
    const float* cw1  = (const float*)d_in[11];
    const float* cb1  = (const float*)d_in[12];
    const float* cw2  = (const float*)d_in[13];
    const float* cb2  = (const float*)d_in[14];
    const float* cw3  = (const float*)d_in[15];
    const float* cb3  = (const float*)d_in[16];
    float* out = (float*)d_out;

    float *h, *agg, *t1, *feats, *z1, *z2;
    int *src, *dst, *bat, *deg, *rowptr, *cursor, *col;
    cudaGetSymbolAddress((void**)&h, g_h);
    cudaGetSymbolAddress((void**)&agg, g_agg);
    cudaGetSymbolAddress((void**)&t1, g_t1);
    cudaGetSymbolAddress((void**)&feats, g_feats);
    cudaGetSymbolAddress((void**)&z1, g_z1);
    cudaGetSymbolAddress((void**)&z2, g_z2);
    cudaGetSymbolAddress((void**)&src, g_src);
    cudaGetSymbolAddress((void**)&dst, g_dst);
    cudaGetSymbolAddress((void**)&bat, g_batch);
    cudaGetSymbolAddress((void**)&deg, g_deg);
    cudaGetSymbolAddress((void**)&rowptr, g_rowptr);
    cudaGetSymbolAddress((void**)&cursor, g_cursor);
    cudaGetSymbolAddress((void**)&col, g_col);

    // 1) index dtype detect + convert
    k_detect<<<1, 32>>>((const unsigned long long*)edges);
    {
        int n = (EE > NN) ? EE : NN;
        k_convert<<<(n + 255) / 256, 256>>>(edges, batch);
    }

    // 2) CSR build (dst-major, col = src)
    k_zero_int<<<(NN + 255) / 256, 256>>>(deg, NN);
    k_count<<<(EE + 255) / 256, 256>>>(dst, deg);
    k_scan<<<1, 1024>>>(deg, rowptr, NN);
    k_copy_int<<<(NN + 255) / 256, 256>>>(rowptr, cursor, NN);
    k_fill<<<(EE + 255) / 256, 256>>>(src, dst, cursor, col);

    // 3) layer 0 (input width 9)
    k_aggregate<<<NN, 32>>>(x, agg, rowptr, col, INF);
    sgemm(NN, HID, INF, agg, w1_0, b1_0, t1, 1);
    sgemm(NN, HID, HID, t1, w2_0, b2_0, h, 1);  // fused inter-layer relu

    // 4) layers 1..4
    for (int i = 0; i < 4; i++) {
        k_aggregate_v4<<<NN, 160>>>(h, agg, rowptr, col);
        sgemm(NN, HID, HID, agg, w1_r + i * HID * HID, b1_r + i * HID, t1, 1);
        sgemm(NN, HID, HID, t1, w2_r + i * HID * HID, b2_r + i * HID, h, (i < 3) ? 1 : 0);
    }

    // 5) global_add_pool
    k_zero_float<<<(NG * HID + 255) / 256, 256>>>(feats, NG * HID);
    k_pool<<<(NN * HID + 255) / 256, 256>>>(h, bat, feats);

    // 6) classifier MLP
    sgemm(NG, CHID, HID, feats, cw1, cb1, z1, 1);
    sgemm(NG, CHID, CHID, z1, cw2, cb2, z2, 1);
    sgemm(NG, NT, CHID, z2, cw3, cb3, out, 0);
}

// round 3
// speedup vs baseline: 1.1543x; 1.1543x over previous
#include <cuda_runtime.h>

// Problem constants (match reference)
#define NN   30000
#define EE   300000
#define NG   512
#define HID  600
#define INF  9
#define NT   128
#define CHID 256

// ---------------- device scratch (allocation-free rule: device globals) ----
__device__ float g_h[NN * HID];
__device__ float g_agg[NN * HID];
__device__ float g_t1[NN * HID];
__device__ float g_feats[NG * HID];
__device__ float g_z1[NG * CHID];
__device__ float g_z2[NG * CHID];

__device__ int g_src[EE];
__device__ int g_dst[EE];
__device__ int g_batch[NN];
__device__ int g_deg[NN];
__device__ int g_rowptr[NN + 1];
__device__ int g_cursor[NN];
__device__ int g_col[EE];
__device__ int g_is64;

// ---------------- index dtype detection + conversion ----------------------
__global__ void k_detect(const unsigned long long* __restrict__ p) {
    if (threadIdx.x == 0 && blockIdx.x == 0) {
        int is64 = 1;
        for (int i = 0; i < 256; i++)
            if (p[i] >> 32) { is64 = 0; break; }
        g_is64 = is64;
    }
}

__global__ void k_convert(const void* __restrict__ edges,
                          const void* __restrict__ batch) {
    int i = blockIdx.x * blockDim.x + threadIdx.x;
    int is64 = g_is64;
    if (i < EE) {
        if (is64) {
            const long long* p = (const long long*)edges;
            g_src[i] = (int)p[i];
            g_dst[i] = (int)p[EE + i];
        } else {
            const int* p = (const int*)edges;
            g_src[i] = p[i];
            g_dst[i] = p[EE + i];
        }
    }
    if (i < NN) {
        if (is64) {
            const long long* p = (const long long*)batch;
            g_batch[i] = (int)p[i];
        } else {
            const int* p = (const int*)batch;
            g_batch[i] = p[i];
        }
    }
}

// ---------------- small utility kernels ------------------------------------
__global__ void k_zero_int(int* p, int n) {
    int i = blockIdx.x * blockDim.x + threadIdx.x;
    if (i < n) p[i] = 0;
}
__global__ void k_zero_float(float* p, int n) {
    int i = blockIdx.x * blockDim.x + threadIdx.x;
    if (i < n) p[i] = 0.f;
}
__global__ void k_copy_int(const int* __restrict__ a, int* __restrict__ b, int n) {
    int i = blockIdx.x * blockDim.x + threadIdx.x;
    if (i < n) b[i] = a[i];
}

// ---------------- CSR build (dst-major) ------------------------------------
__global__ void k_count(const int* __restrict__ dst, int* __restrict__ deg) {
    int i = blockIdx.x * blockDim.x + threadIdx.x;
    if (i < EE) atomicAdd(&deg[dst[i]], 1);
}

__global__ void k_scan(const int* __restrict__ in, int* __restrict__ out, int n) {
    __shared__ int s[1024];
    __shared__ int s_carry;
    int tid = threadIdx.x;
    if (tid == 0) s_carry = 0;
    __syncthreads();
    for (int base = 0; base < n; base += 1024) {
        int i = base + tid;
        int v = (i < n) ? in[i] : 0;
        s[tid] = v;
        __syncthreads();
        for (int off = 1; off < 1024; off <<= 1) {
            int t = (tid >= off) ? s[tid - off] : 0;
            __syncthreads();
            s[tid] += t;
            __syncthreads();
        }
        int c = s_carry;
        if (i < n) out[i] = c + s[tid] - v;
        __syncthreads();
        if (tid == 0) s_carry = c + s[1023];
        __syncthreads();
    }
    if (tid == 0) out[n] = s_carry;
}

__global__ void k_fill(const int* __restrict__ src, const int* __restrict__ dst,
                       int* __restrict__ cursor, int* __restrict__ col) {
    int i = blockIdx.x * blockDim.x + threadIdx.x;
    if (i < EE) {
        int p = atomicAdd(&cursor[dst[i]], 1);
        col[p] = src[i];
    }
}

// ---------------- aggregation --------------------------------------------
__global__ void k_aggregate(const float* __restrict__ h, float* __restrict__ agg,
                            const int* __restrict__ rowptr,
                            const int* __restrict__ col, int width) {
    __shared__ int s_nbr[64];
    int node = blockIdx.x;
    int f = threadIdx.x;
    int CH = (blockDim.x < 64) ? blockDim.x : 64;
    int start = rowptr[node], end = rowptr[node + 1];
    float acc = (f < width) ? h[node * width + f] : 0.f;
    for (int base = start; base < end; base += CH) {
        int cnt = end - base;
        if (cnt > CH) cnt = CH;
        if ((int)threadIdx.x < cnt) s_nbr[threadIdx.x] = col[base + threadIdx.x];
        __syncthreads();
        if (f < width) {
            for (int j = 0; j < cnt; j++)
                acc += h[s_nbr[j] * width + f];
        }
        __syncthreads();
    }
    if (f < width) agg[node * width + f] = acc;
}

__global__ void k_aggregate_v4(const float* __restrict__ h, float* __restrict__ agg,
                               const int* __restrict__ rowptr,
                               const int* __restrict__ col) {
    __shared__ int s_nbr[32];
    int node = blockIdx.x;
    int f4 = threadIdx.x;                  // 0..159, use first 150
    int start = rowptr[node], end = rowptr[node + 1];
    const float4* hv = (const float4*)h;
    float4 acc;
    if (f4 < 150) acc = hv[node * 150 + f4];
    else acc = make_float4(0.f, 0.f, 0.f, 0.f);
    for (int base = start; base < end; base += 32) {
        int cnt = end - base;
        if (cnt > 32) cnt = 32;
        if ((int)threadIdx.x < cnt) s_nbr[threadIdx.x] = col[base + threadIdx.x];
        __syncthreads();
        if (f4 < 150) {
            for (int j = 0; j < cnt; j++) {
                float4 v = hv[s_nbr[j] * 150 + f4];
                acc.x += v.x; acc.y += v.y; acc.z += v.z; acc.w += v.w;
            }
        }
        __syncthreads();
    }
    if (f4 < 150) ((float4*)agg)[node * 150 + f4] = acc;
}

// ---------------- pooling --------------------------------------------------
__global__ void k_pool(const float* __restrict__ h, const int* __restrict__ batch,
                       float* __restrict__ feats) {
    int idx = blockIdx.x * blockDim.x + threadIdx.x;
    if (idx >= NN * HID) return;
    int n = idx / HID;
    int f = idx - n * HID;
    atomicAdd(&feats[batch[n] * HID + f], h[idx]);
}

// ---------------- FFMA SGEMM (small GEMMs: K=9 layer0, classifier) ---------
#define BM 128
#define BN 128
#define BK 8

__global__ __launch_bounds__(256)
void k_sgemm(int M, int N, int K,
             const float* __restrict__ A, const float* __restrict__ B,
             const float* __restrict__ bias, float* __restrict__ C, int relu) {
    __shared__ float As[BK][BM + 4];
    __shared__ float Bs[BK][BN];

    int tid = threadIdx.x;
    int tx = tid & 15;
    int ty = tid >> 4;
    int m0 = blockIdx.y * BM;
    int n0 = blockIdx.x * BN;

    float acc[8][8];
#pragma unroll
    for (int i = 0; i < 8; i++)
#pragma unroll
        for (int j = 0; j < 8; j++) acc[i][j] = 0.f;

    for (int k0 = 0; k0 < K; k0 += BK) {
#pragma unroll
        for (int i = 0; i < 4; i++) {
            int e = tid * 4 + i;
            int m = e >> 3, k = e & 7;
            int gm = m0 + m, gk = k0 + k;
            As[k][m] = (gm < M && gk < K) ? A[gm * K + gk] : 0.f;
        }
#pragma unroll
        for (int i = 0; i < 4; i++) {
            int e = tid * 4 + i;
            int k = e >> 7, n = e & 127;
            int gn = n0 + n, gk = k0 + k;
            Bs[k][n] = (gn < N && gk < K) ? B[gk * N + gn] : 0.f;
        }
        __syncthreads();

#pragma unroll
        for (int k = 0; k < BK; k++) {
            float4 a0 = *(const float4*)&As[k][ty * 4];
            float4 a1 = *(const float4*)&As[k][64 + ty * 4];
            float4 b0 = *(const float4*)&Bs[k][tx * 4];
            float4 b1 = *(const float4*)&Bs[k][64 + tx * 4];
            float a[8] = {a0.x, a0.y, a0.z, a0.w, a1.x, a1.y, a1.z, a1.w};
            float b[8] = {b0.x, b0.y, b0.z, b0.w, b1.x, b1.y, b1.z, b1.w};
#pragma unroll
            for (int i = 0; i < 8; i++)
#pragma unroll
                for (int j = 0; j < 8; j++)
                    acc[i][j] = fmaf(a[i], b[j], acc[i][j]);
        }
        __syncthreads();
    }

#pragma unroll
    for (int i = 0; i < 8; i++) {
        int r = (i < 4) ? (ty * 4 + i) : (64 + ty * 4 + (i - 4));
        int gm = m0 + r;
        if (gm >= M) continue;
#pragma unroll
        for (int j = 0; j < 8; j++) {
            int c = (j < 4) ? (tx * 4 + j) : (64 + tx * 4 + (j - 4));
            int gn = n0 + c;
            if (gn >= N) continue;
            float v = acc[i][j] + bias[gn];
            if (relu) v = fmaxf(v, 0.f);
            C[gm * N + gn] = v;
        }
    }
}

// ---------------- 3xTF32 tensor-core GEMM ----------------------------------
// C = act(A[M,K] @ B[K,N] + bias), fp32 in/out, 3-pass tf32 split for accuracy.
// 128x128x16 block tile, 256 threads (8 warps as 4x2, warp tile 32x64),
// double-buffered smem, pad-8 rows => conflict-free fragment LDS.
#define GBM 128
#define GBN 128
#define GBK 16
#define GLDA (GBM + 8)   // 136
#define GLDB (GBN + 8)   // 136
// smem floats: sA[2][2][16][136] + sB[2][2][16][136]
#define GSM_A_FLOATS (2 * 2 * GBK * GLDA)
#define GSM_TOTAL_BYTES ((GSM_A_FLOATS * 2) * 4)

#define SA(buf, hl, k, m) sA[(((buf) * 2 + (hl)) * GBK + (k)) * GLDA + (m)]
#define SB(buf, hl, k, n) sB[(((buf) * 2 + (hl)) * GBK + (k)) * GLDB + (n)]

__device__ __forceinline__ unsigned f2tf32(float x) {
    unsigned r;
    asm("cvt.rna.tf32.f32 %0, %1;" : "=r"(r) : "f"(x));
    return r;
}

__device__ __forceinline__ void mma_tf32(float* d, const unsigned* a,
                                         unsigned b0, unsigned b1) {
    asm volatile(
        "mma.sync.aligned.m16n8k8.row.col.f32.tf32.tf32.f32 "
        "{%0,%1,%2,%3}, {%4,%5,%6,%7}, {%8,%9}, {%0,%1,%2,%3};\n"
        : "+f"(d[0]), "+f"(d[1]), "+f"(d[2]), "+f"(d[3])
        : "r"(a[0]), "r"(a[1]), "r"(a[2]), "r"(a[3]), "r"(b0), "r"(b1));
}

__global__ __launch_bounds__(256, 1)
void k_gemm_tf32(int M, int N, int K,
                 const float* __restrict__ A, const float* __restrict__ B,
                 const float* __restrict__ bias, float* __restrict__ C, int relu) {
    extern __shared__ float sm_dyn[];
    float* sA = sm_dyn;
    float* sB = sm_dyn + GSM_A_FLOATS;

    int tid = threadIdx.x;
    int lane = tid & 31;
    int warp = tid >> 5;
    int wm = (warp >> 1) * 32;   // warp row offset in tile
    int wn = (warp & 1) * 64;    // warp col offset in tile
    int lq = lane >> 2;          // 0..7
    int lr = lane & 3;           // 0..3

    int m0 = blockIdx.y * GBM;
    int n0 = blockIdx.x * GBN;
    bool m_full = (m0 + GBM <= M);
    bool n_full = (n0 + GBN <= N);

    // global load mappings
    int a_m = tid >> 1;               // 0..127
    int a_k = (tid & 1) * 8;          // 0 or 8
    int b_k = tid >> 4;               // 0..15
    int b_n = (tid & 15) * 8;         // 0..120

    float acc[2][8][4];
#pragma unroll
    for (int i = 0; i < 2; i++)
#pragma unroll
        for (int j = 0; j < 8; j++)
#pragma unroll
            for (int c = 0; c < 4; c++) acc[i][j][c] = 0.f;

    float ra[8], rb[8];
    int NIT = (K + GBK - 1) / GBK;

    // ---- prologue: load + STS tile 0 ----
    {
        int k0 = 0;
        bool k_full = (GBK <= K);
        if (m_full && k_full) {
            const float* p = &A[(m0 + a_m) * K + k0 + a_k];
            float4 v0 = *(const float4*)p;
            float4 v1 = *(const float4*)(p + 4);
            ra[0] = v0.x; ra[1] = v0.y; ra[2] = v0.z; ra[3] = v0.w;
            ra[4] = v1.x; ra[5] = v1.y; ra[6] = v1.z; ra[7] = v1.w;
        } else {
#pragma unroll
            for (int i = 0; i < 8; i++) {
                int gm = m0 + a_m, gk = k0 + a_k + i;
                ra[i] = (gm < M && gk < K) ? A[gm * K + gk] : 0.f;
            }
        }
        if (n_full && k_full) {
            const float* p = &B[(k0 + b_k) * N + n0 + b_n];
            float4 v0 = *(const float4*)p;
            float4 v1 = *(const float4*)(p + 4);
            rb[0] = v0.x; rb[1] = v0.y; rb[2] = v0.z; rb[3] = v0.w;
            rb[4] = v1.x; rb[5] = v1.y; rb[6] = v1.z; rb[7] = v1.w;
        } else {
#pragma unroll
            for (int i = 0; i < 8; i++) {
                int gk = k0 + b_k, gn = n0 + b_n + i;
                rb[i] = (gk < K && gn < N) ? B[gk * N + gn] : 0.f;
            }
        }
#pragma unroll
        for (int i = 0; i < 8; i++) {
            unsigned hi = f2tf32(ra[i]);
            float lo = ra[i] - __uint_as_float(hi);
            SA(0, 0, a_k + i, a_m) = __uint_as_float(hi);
            SA(0, 1, a_k + i, a_m) = __uint_as_float(f2tf32(lo));
        }
#pragma unroll
        for (int i = 0; i < 8; i++) {
            unsigned hi = f2tf32(rb[i]);
            float lo = rb[i] - __uint_as_float(hi);
            SB(0, 0, b_k, b_n + i) = __uint_as_float(hi);
            SB(0, 1, b_k, b_n + i) = __uint_as_float(f2tf32(lo));
        }
    }
    __syncthreads();

    int buf = 0;
    for (int it = 0; it < NIT; it++) {
        bool has_next = (it + 1 < NIT);
        // ---- prefetch next tile into registers ----
        if (has_next) {
            int k0 = (it + 1) * GBK;
            bool k_full = (k0 + GBK <= K);
            if (m_full && k_full) {
                const float* p = &A[(m0 + a_m) * K + k0 + a_k];
                float4 v0 = *(const float4*)p;
                float4 v1 = *(const float4*)(p + 4);
                ra[0] = v0.x; ra[1] = v0.y; ra[2] = v0.z; ra[3] = v0.w;
                ra[4] = v1.x; ra[5] = v1.y; ra[6] = v1.z; ra[7] = v1.w;
            } else {
#pragma unroll
                for (int i = 0; i < 8; i++) {
                    int gm = m0 + a_m, gk = k0 + a_k + i;
                    ra[i] = (gm < M && gk < K) ? A[gm * K + gk] : 0.f;
                }
            }
            if (n_full && k_full) {
                const float* p = &B[(k0 + b_k) * N + n0 + b_n];
                float4 v0 = *(const float4*)p;
                float4 v1 = *(const float4*)(p + 4);
                rb[0] = v0.x; rb[1] = v0.y; rb[2] = v0.z; rb[3] = v0.w;
                rb[4] = v1.x; rb[5] = v1.y; rb[6] = v1.z; rb[7] = v1.w;
            } else {
#pragma unroll
                for (int i = 0; i < 8; i++) {
                    int gk = k0 + b_k, gn = n0 + b_n + i;
                    rb[i] = (gk < K && gn < N) ? B[gk * N + gn] : 0.f;
                }
            }
        }

        // ---- compute on current buffer ----
#pragma unroll
        for (int kk = 0; kk < GBK; kk += 8) {
            int tk = kk + lr;
            unsigned ah[2][4], al[2][4];
#pragma unroll
            for (int i = 0; i < 2; i++) {
                int mi = wm + i * 16 + lq;
                ah[i][0] = __float_as_uint(SA(buf, 0, tk, mi));
                ah[i][1] = __float_as_uint(SA(buf, 0, tk, mi + 8));
                ah[i][2] = __float_as_uint(SA(buf, 0, tk + 4, mi));
                ah[i][3] = __float_as_uint(SA(buf, 0, tk + 4, mi + 8));
                al[i][0] = __float_as_uint(SA(buf, 1, tk, mi));
                al[i][1] = __float_as_uint(SA(buf, 1, tk, mi + 8));
                al[i][2] = __float_as_uint(SA(buf, 1, tk + 4, mi));
                al[i][3] = __float_as_uint(SA(buf, 1, tk + 4, mi + 8));
            }
#pragma unroll
            for (int j = 0; j < 8; j++) {
                int nn = wn + j * 8 + lq;
                unsigned bh0 = __float_as_uint(SB(buf, 0, tk, nn));
                unsigned bh1 = __float_as_uint(SB(buf, 0, tk + 4, nn));
                unsigned bl0 = __float_as_uint(SB(buf, 1, tk, nn));
                unsigned bl1 = __float_as_uint(SB(buf, 1, tk + 4, nn));
#pragma unroll
                for (int i = 0; i < 2; i++) {
                    mma_tf32(acc[i][j], ah[i], bh0, bh1);
                    mma_tf32(acc[i][j], ah[i], bl0, bl1);
                    mma_tf32(acc[i][j], al[i], bh0, bh1);
                }
            }
        }

        // ---- convert + STS next tile into other buffer ----
        if (has_next) {
            int ob = buf ^ 1;
#pragma unroll
            for (int i = 0; i < 8; i++) {
                unsigned hi = f2tf32(ra[i]);
                float lo = ra[i] - __uint_as_float(hi);
                SA(ob, 0, a_k + i, a_m) = __uint_as_float(hi);
                SA(ob, 1, a_k + i, a_m) = __uint_as_float(f2tf32(lo));
            }
#pragma unroll
            for (int i = 0; i < 8; i++) {
                unsigned hi = f2tf32(rb[i]);
                float lo = rb[i] - __uint_as_float(hi);
                SB(ob, 0, b_k, b_n + i) = __uint_as_float(hi);
                SB(ob, 1, b_k, b_n + i) = __uint_as_float(f2tf32(lo));
            }
        }
        __syncthreads();
        buf ^= 1;
    }

    // ---- epilogue: bias + optional relu ----
#pragma unroll
    for (int i = 0; i < 2; i++) {
#pragma unroll
        for (int c = 0; c < 4; c++) {
            int row = m0 + wm + i * 16 + lq + ((c >= 2) ? 8 : 0);
            if (row >= M) continue;
#pragma unroll
            for (int j = 0; j < 8; j++) {
                int col = n0 + wn + j * 8 + 2 * lr + (c & 1);
                if (col >= N) continue;
                float v = acc[i][j][c] + bias[col];
                if (relu) v = fmaxf(v, 0.f);
                C[row * N + col] = v;
            }
        }
    }
}

// ---------------- host orchestration ---------------------------------------
static inline void sgemm(int M, int N, int K, const float* A, const float* B,
                         const float* bias, float* C, int relu) {
    dim3 grid((N + BN - 1) / BN, (M + BM - 1) / BM);
    k_sgemm<<<grid, 256>>>(M, N, K, A, B, bias, C, relu);
}

static inline void gemm_tf32(int M, int N, int K, const float* A, const float* B,
                             const float* bias, float* C, int relu) {
    dim3 grid((N + GBN - 1) / GBN, (M + GBM - 1) / GBM);
    k_gemm_tf32<<<grid, 256, GSM_TOTAL_BYTES>>>(M, N, K, A, B, bias, C, relu);
}

extern "C" void kernel_launch(void* const* d_in, const int* in_sizes, int n_in,
                              void* d_out, int out_size) {
    const float* x      = (const float*)d_in[0];
    const void*  edges  = d_in[1];
    const void*  batch  = d_in[2];
    const float* w1_0 = (const float*)d_in[3];
    const float* b1_0 = (const float*)d_in[4];
    const float* w2_0 = (const float*)d_in[5];
    const float* b2_0 = (const float*)d_in[6];
    const float* w1_r = (const float*)d_in[7];
    const float* b1_r = (const float*)d_in[8];
    const float* w2_r = (const float*)d_in[9];
    const float* b2_r = (const float*)d_in[10];
    const float* cw1  = (const float*)d_in[11];
    const float* cb1  = (const float*)d_in[12];
    const float* cw2  = (const float*)d_in[13];
    const float* cb2  = (const float*)d_in[14];
    const float* cw3  = (const float*)d_in[15];
    const float* cb3  = (const float*)d_in[16];
    float* out = (float*)d_out;

    float *h, *agg, *t1, *feats, *z1, *z2;
    int *src, *dst, *bat, *deg, *rowptr, *cursor, *col;
    cudaGetSymbolAddress((void**)&h, g_h);
    cudaGetSymbolAddress((void**)&agg, g_agg);
    cudaGetSymbolAddress((void**)&t1, g_t1);
    cudaGetSymbolAddress((void**)&feats, g_feats);
    cudaGetSymbolAddress((void**)&z1, g_z1);
    cudaGetSymbolAddress((void**)&z2, g_z2);
    cudaGetSymbolAddress((void**)&src, g_src);
    cudaGetSymbolAddress((void**)&dst, g_dst);
    cudaGetSymbolAddress((void**)&bat, g_batch);
    cudaGetSymbolAddress((void**)&deg, g_deg);
    cudaGetSymbolAddress((void**)&rowptr, g_rowptr);
    cudaGetSymbolAddress((void**)&cursor, g_cursor);
    cudaGetSymbolAddress((void**)&col, g_col);

    // allow 68 KB dynamic smem for the tf32 GEMM (idempotent, cheap)
    cudaFuncSetAttribute(k_gemm_tf32, cudaFuncAttributeMaxDynamicSharedMemorySize,
                         GSM_TOTAL_BYTES);

    // 1) index dtype detect + convert
    k_detect<<<1, 32>>>((const unsigned long long*)edges);
    {
        int n = (EE > NN) ? EE : NN;
        k_convert<<<(n + 255) / 256, 256>>>(edges, batch);
    }

    // 2) CSR build (dst-major, col = src)
    k_zero_int<<<(NN + 255) / 256, 256>>>(deg, NN);
    k_count<<<(EE + 255) / 256, 256>>>(dst, deg);
    k_scan<<<1, 1024>>>(deg, rowptr, NN);
    k_copy_int<<<(NN + 255) / 256, 256>>>(rowptr, cursor, NN);
    k_fill<<<(EE + 255) / 256, 256>>>(src, dst, cursor, col);

    // 3) layer 0 (input width 9) — FFMA path for K=9
    k_aggregate<<<NN, 32>>>(x, agg, rowptr, col, INF);
    sgemm(NN, HID, INF, agg, w1_0, b1_0, t1, 1);
    gemm_tf32(NN, HID, HID, t1, w2_0, b2_0, h, 1);  // fused inter-layer relu

    // 4) layers 1..4 — tensor-core GEMMs
    for (int i = 0; i < 4; i++) {
        k_aggregate_v4<<<NN, 160>>>(h, agg, rowptr, col);
        gemm_tf32(NN, HID, HID, agg, w1_r + i * HID * HID, b1_r + i * HID, t1, 1);
        gemm_tf32(NN, HID, HID, t1, w2_r + i * HID * HID, b2_r + i * HID, h, (i < 3) ? 1 : 0);
    }

    // 5) global_add_pool
    k_zero_float<<<(NG * HID + 255) / 256, 256>>>(feats, NG * HID);
    k_pool<<<(NN * HID + 255) / 256, 256>>>(h, bat, feats);

    // 6) classifier MLP (small — FFMA path)
    sgemm(NG, CHID, HID, feats, cw1, cb1, z1, 1);
    sgemm(NG, CHID, CHID, z1, cw2, cb2, z2, 1);
    sgemm(NG, NT, CHID, z2, cw3, cb3, out, 0);
}